// round 5
// baseline (speedup 1.0000x reference)
#include <cuda_runtime.h>

// SSIM loss, 7x7 valid window, [32,3,512,512] fp32, scalar out.
// R5: warp-specialized CTA (8 producer warps / 8 consumer warps, named barrier).
// Producers: packed 2-column vertical running sums (LDG.64, f32x2 math,
// STS.128 interleaved stores). Consumers: 8 outputs/thread, group-padded
// conflict-free LDS.128 window loads (ulonglong2 -> free f32x2 pairs),
// sliding 7-window + folded SSIM. Double-buffered 4-row subchunks.

#define IW     512
#define OH     506
#define OW     506
#define BR     88
#define NBANDS 6
#define NIMG   96
#define NCTA   (NBANDS * NIMG)   // 576
#define RSX    640               // float2 per padded row: 64 groups * 10
#define PLANEQ (4 * RSX)         // one quantity-pair plane (4 rows), float2 units
#define BUFQ   (2 * PLANEQ)      // one buffer: plane01 + plane23
#define SMEM_F2 (2 * BUFQ + 16)  // +pad for g=63 overflow reads
#define SMEM_BYTES (SMEM_F2 * 8) // 82,048 B -> 2 CTAs/SM

typedef unsigned long long u64;

__device__ float g_partials[NCTA];
__device__ unsigned int g_count = 0;

__device__ __forceinline__ u64 add2(u64 a, u64 b) {
    u64 r; asm("add.rn.f32x2 %0, %1, %2;" : "=l"(r) : "l"(a), "l"(b)); return r;
}
__device__ __forceinline__ u64 mul2(u64 a, u64 b) {
    u64 r; asm("mul.rn.f32x2 %0, %1, %2;" : "=l"(r) : "l"(a), "l"(b)); return r;
}
__device__ __forceinline__ u64 fma2(u64 a, u64 b, u64 c) {
    u64 r; asm("fma.rn.f32x2 %0, %1, %2, %3;" : "=l"(r) : "l"(a), "l"(b), "l"(c)); return r;
}
__device__ __forceinline__ void unpack2(u64 v, float& a, float& b) {
    asm("mov.b64 {%0, %1}, %2;" : "=f"(a), "=f"(b) : "l"(v));
}
#define NEG1X2 0xBF800000BF800000ull

// whole-block named barrier usable from divergent (but warp-uniform) paths
__device__ __forceinline__ void block_bar() {
    asm volatile("bar.sync 0, 512;" ::: "memory");
}

__device__ __forceinline__ float ssim_term(float sx, float sy, float ss, float sxy) {
    const float c1big = 0.2401f;   // 2401 * (0.01)^2
    const float c2big = 2.1168f;   // 2352 * (0.03)^2
    float t1 = sx * sy;
    float a1 = fmaf(t1, 2.0f, c1big);
    float b1 = fmaf(sx, sx, c1big);
    b1 = fmaf(sy, sy, b1);
    float a2 = fmaf(sxy, 98.0f, c2big);
    a2 = fmaf(t1, -2.0f, a2);
    float b2 = fmaf(ss, 49.0f, c2big);
    b2 = fmaf(sx, -sx, b2);
    b2 = fmaf(sy, -sy, b2);
    return __fdividef(a1 * a2, b1 * b2);
}

struct PState { u64 VX, VY, VS, VXY; };

// Producer: 4 rows of vertical running sums for 2 packed columns.
template <bool GUARD>
__device__ __forceinline__ void vert4(
    PState& s, float2* __restrict__ sb,
    const float* __restrict__ xp, const float* __restrict__ yp,
    int rb, int rmax, int c, int sidx) {
#pragma unroll
    for (int j = 0; j < 4; ++j) {
        int r = rb + j;
        if (!GUARD || r <= rmax) {
            u64 xn = *(const u64*)(xp + (size_t)(r + 6) * IW + c);
            u64 yn = *(const u64*)(yp + (size_t)(r + 6) * IW + c);
            u64 xo = *(const u64*)(xp + (size_t)r * IW + c);
            u64 yo = *(const u64*)(yp + (size_t)r * IW + c);
            s.VX = add2(s.VX, xn); s.VY = add2(s.VY, yn);
            s.VS = fma2(xn, xn, s.VS); s.VS = fma2(yn, yn, s.VS);
            s.VXY = fma2(xn, yn, s.VXY);
            float vx0, vx1, vy0, vy1, vs0, vs1, vq0, vq1;
            unpack2(s.VX, vx0, vx1); unpack2(s.VY, vy0, vy1);
            unpack2(s.VS, vs0, vs1); unpack2(s.VXY, vq0, vq1);
            *(float4*)(sb + j * RSX + sidx)          = make_float4(vx0, vy0, vx1, vy1);
            *(float4*)(sb + PLANEQ + j * RSX + sidx) = make_float4(vs0, vq0, vs1, vq1);
            u64 nxo = mul2(xo, NEG1X2), nyo = mul2(yo, NEG1X2);
            s.VX = add2(s.VX, nxo); s.VY = add2(s.VY, nyo);
            s.VS = fma2(nxo, xo, s.VS); s.VS = fma2(nyo, yo, s.VS);
            s.VXY = fma2(nxo, yo, s.VXY);
        }
    }
}

// Consumer: 8 outputs (1 row x 8 cols) via conflict-free LDS.128 window.
template <bool GUARD>
__device__ __forceinline__ void horiz8(
    const float2* __restrict__ sb, int rb, int rmax,
    int jrow, int g, float& acc) {
    if (GUARD && rb + jrow > rmax) return;
    const float2* rowA = sb + jrow * RSX + 10 * g;
    const float2* rowB = rowA + PLANEQ;
    // overflow loads for g=63 redirected to a safe (unused) valid address
    const int ofs2 = (g < 63) ? 5 : 1;

    u64 wa[14];
    {
        const ulonglong2* p = (const ulonglong2*)rowA;
#pragma unroll
        for (int i = 0; i < 4; ++i) { ulonglong2 t = p[i];        wa[2*i]   = t.x; wa[2*i+1] = t.y; }
#pragma unroll
        for (int i = 0; i < 3; ++i) { ulonglong2 t = p[ofs2 + i]; wa[8+2*i] = t.x; wa[9+2*i] = t.y; }
    }
    u64 Bout[8];
    {
        u64 B = wa[0];
#pragma unroll
        for (int k = 1; k < 7; ++k) B = add2(B, wa[k]);
        Bout[0] = B;
#pragma unroll
        for (int i = 1; i < 8; ++i) {
            B = add2(B, wa[i + 6]);
            B = fma2(wa[i - 1], NEG1X2, B);
            Bout[i] = B;
        }
    }
    u64 wb[14];
    {
        const ulonglong2* p = (const ulonglong2*)rowB;
#pragma unroll
        for (int i = 0; i < 4; ++i) { ulonglong2 t = p[i];        wb[2*i]   = t.x; wb[2*i+1] = t.y; }
#pragma unroll
        for (int i = 0; i < 3; ++i) { ulonglong2 t = p[ofs2 + i]; wb[8+2*i] = t.x; wb[9+2*i] = t.y; }
    }
    const int T = (OW - 8 * g < 8) ? (OW - 8 * g) : 8;
    u64 B = wb[0];
#pragma unroll
    for (int k = 1; k < 7; ++k) B = add2(B, wb[k]);
    {
        float sx, sy, ss, sxy;
        unpack2(Bout[0], sx, sy); unpack2(B, ss, sxy);
        acc += ssim_term(sx, sy, ss, sxy);
    }
#pragma unroll
    for (int i = 1; i < 8; ++i) {
        B = add2(B, wb[i + 6]);
        B = fma2(wb[i - 1], NEG1X2, B);
        if (i < T) {
            float sx, sy, ss, sxy;
            unpack2(Bout[i], sx, sy); unpack2(B, ss, sxy);
            acc += ssim_term(sx, sy, ss, sxy);
        }
    }
}

template <bool GUARD>
__device__ __forceinline__ float band_loop(
    const float* __restrict__ xp, const float* __restrict__ yp,
    float2* __restrict__ sm, int r0, int rmax, int tid) {
    float acc = 0.f;
    const int nsub = GUARD ? (((rmax - r0) >> 2) + 1) : (BR / 4);

    if (tid < 256) {
        // ---------------- producers ----------------
        const int p = tid;
        const int c = 2 * p;
        const int sidx = 10 * (p >> 2) + 2 * (p & 3);  // float2 idx in padded row
        PState s; s.VX = 0; s.VY = 0; s.VS = 0; s.VXY = 0;
#pragma unroll
        for (int k = 0; k < 6; ++k) {
            u64 x = *(const u64*)(xp + (size_t)(r0 + k) * IW + c);
            u64 y = *(const u64*)(yp + (size_t)(r0 + k) * IW + c);
            s.VX = add2(s.VX, x); s.VY = add2(s.VY, y);
            s.VS = fma2(x, x, s.VS); s.VS = fma2(y, y, s.VS);
            s.VXY = fma2(x, y, s.VXY);
        }
        vert4<false>(s, sm, xp, yp, r0, rmax, c, sidx);  // subchunk 0 -> buf0
        block_bar();
        for (int t = 0; t < nsub; ++t) {
            if (t + 1 < nsub)
                vert4<GUARD>(s, sm + (size_t)((t + 1) & 1) * BUFQ,
                             xp, yp, r0 + 4 * (t + 1), rmax, c, sidx);
            block_bar();
        }
    } else {
        // ---------------- consumers ----------------
        const int q = tid - 256;
        const int jrow = q >> 6;
        const int g = q & 63;
        block_bar();
        for (int t = 0; t < nsub; ++t) {
            horiz8<GUARD>(sm + (size_t)(t & 1) * BUFQ, r0 + 4 * t, rmax, jrow, g, acc);
            block_bar();
        }
    }
    return acc;
}

__global__ __launch_bounds__(512, 2)
void ssim_kernel(const float* __restrict__ X, const float* __restrict__ Y,
                 float* __restrict__ out) {
    extern __shared__ float2 smbuf[];
    __shared__ float wsum[16];
    __shared__ bool isLast;

    const int tid  = threadIdx.x;
    const int band = blockIdx.x;
    const int img  = blockIdx.y;

    const float* __restrict__ xp = X + (size_t)img * (512 * 512);
    const float* __restrict__ yp = Y + (size_t)img * (512 * 512);
    const int r0   = band * BR;
    const int rmax = min(r0 + BR - 1, OH - 1);

    float acc;
    if (rmax == r0 + BR - 1) {
        acc = band_loop<false>(xp, yp, smbuf, r0, rmax, tid);
    } else {
        acc = band_loop<true>(xp, yp, smbuf, r0, rmax, tid);
    }

    // ---- block reduction ----
#pragma unroll
    for (int o = 16; o > 0; o >>= 1)
        acc += __shfl_xor_sync(0xffffffffu, acc, o);
    if ((tid & 31) == 0) wsum[tid >> 5] = acc;
    __syncthreads();

    if (tid == 0) {
        float s = 0.f;
#pragma unroll
        for (int w = 0; w < 16; ++w) s += wsum[w];
        g_partials[img * NBANDS + band] = s;
        __threadfence();
        unsigned int old = atomicAdd(&g_count, 1u);
        isLast = (old == NCTA - 1);
    }
    __syncthreads();

    // ---- deterministic last-block global reduction ----
    if (isLast) {
        float s = 0.f;
        for (int i = tid; i < NCTA; i += 512) s += g_partials[i];
#pragma unroll
        for (int o = 16; o > 0; o >>= 1)
            s += __shfl_xor_sync(0xffffffffu, s, o);
        if ((tid & 31) == 0) wsum[tid >> 5] = s;
        __syncthreads();
        if (tid == 0) {
            float t = 0.f;
#pragma unroll
            for (int w = 0; w < 16; ++w) t += wsum[w];
            out[0] = 1.0f - t * (1.0f / 24579456.0f);  // 96*506*506
            g_count = 0;  // reset for next graph replay
        }
    }
}

extern "C" void kernel_launch(void* const* d_in, const int* in_sizes, int n_in,
                              void* d_out, int out_size) {
    (void)in_sizes; (void)n_in; (void)out_size;
    const float* X = (const float*)d_in[0];
    const float* Y = (const float*)d_in[1];

    cudaFuncSetAttribute(ssim_kernel,
                         cudaFuncAttributeMaxDynamicSharedMemorySize, SMEM_BYTES);

    dim3 grid(NBANDS, NIMG);
    ssim_kernel<<<grid, 512, SMEM_BYTES>>>(X, Y, (float*)d_out);
}

// round 6
// speedup vs baseline: 1.2647x; 1.2647x over previous
#include <cuda_runtime.h>

// SSIM loss, 7x7 valid window, [32,3,512,512] fp32, scalar out.
// R6: R4's merged-phase double-buffered structure (every thread does
// prefetch + horizontal + vertical each barrier interval) with R5's data
// wins: 256 threads/CTA, packed 2-column vertical (LDG.64 + f32x2 + STS.128),
// 8 outputs/thread horizontal via conflict-free padded LDS.128 groups.
// 128-reg budget (launch_bounds 256,2) so nothing spills.

#define IW     512
#define OH     506
#define OW     506
#define BR     88
#define NBANDS 6
#define NIMG   96
#define NCTA   (NBANDS * NIMG)   // 576
#define RSX    640               // float2 per padded row: 64 groups * 10
#define PLANEQ (4 * RSX)         // one plane (4 rows), float2 units
#define BUFQ   (2 * PLANEQ)      // plane01 + plane23
#define SMEM_F2 (2 * BUFQ + 16)  // + pad for g=63 overflow reads
#define SMEM_BYTES (SMEM_F2 * 8) // 82,048 B -> 2 CTAs/SM

typedef unsigned long long u64;

__device__ float g_partials[NCTA];
__device__ unsigned int g_count = 0;

__device__ __forceinline__ u64 add2(u64 a, u64 b) {
    u64 r; asm("add.rn.f32x2 %0, %1, %2;" : "=l"(r) : "l"(a), "l"(b)); return r;
}
__device__ __forceinline__ u64 mul2(u64 a, u64 b) {
    u64 r; asm("mul.rn.f32x2 %0, %1, %2;" : "=l"(r) : "l"(a), "l"(b)); return r;
}
__device__ __forceinline__ u64 fma2(u64 a, u64 b, u64 c) {
    u64 r; asm("fma.rn.f32x2 %0, %1, %2, %3;" : "=l"(r) : "l"(a), "l"(b), "l"(c)); return r;
}
__device__ __forceinline__ void unpack2(u64 v, float& a, float& b) {
    asm("mov.b64 {%0, %1}, %2;" : "=f"(a), "=f"(b) : "l"(v));
}
#define NEG1X2 0xBF800000BF800000ull

__device__ __forceinline__ float ssim_term(float sx, float sy, float ss, float sxy) {
    const float c1big = 0.2401f;   // 2401 * (0.01)^2
    const float c2big = 2.1168f;   // 2352 * (0.03)^2
    float t1 = sx * sy;
    float a1 = fmaf(t1, 2.0f, c1big);
    float b1 = fmaf(sx, sx, c1big);
    b1 = fmaf(sy, sy, b1);
    float a2 = fmaf(sxy, 98.0f, c2big);
    a2 = fmaf(t1, -2.0f, a2);
    float b2 = fmaf(ss, 49.0f, c2big);
    b2 = fmaf(sx, -sx, b2);
    b2 = fmaf(sy, -sy, b2);
    return __fdividef(a1 * a2, b1 * b2);
}

template <bool GUARD>
__device__ __forceinline__ void prefetch4(
    const float* __restrict__ xp, const float* __restrict__ yp,
    u64* nx, u64* ny, int rbn, int rmax, int c) {
#pragma unroll
    for (int j = 0; j < 4; ++j) {
        if (!GUARD || rbn + j <= rmax) {
            nx[j] = *(const u64*)(xp + (size_t)(rbn + j + 6) * IW + c);
            ny[j] = *(const u64*)(yp + (size_t)(rbn + j + 6) * IW + c);
        }
    }
}

// Vertical: 4 rows of packed 2-column running sums into buffer sb.
template <bool GUARD>
__device__ __forceinline__ void vert4(
    u64& VX, u64& VY, u64& VS, u64& VXY,
    float2* __restrict__ sb, const u64* nx, const u64* ny,
    const float* __restrict__ xp, const float* __restrict__ yp,
    int rb, int rmax, int c, int sidx) {
#pragma unroll
    for (int j = 0; j < 4; ++j) {
        int r = rb + j;
        if (!GUARD || r <= rmax) {
            u64 xn = nx[j], yn = ny[j];
            VX = add2(VX, xn); VY = add2(VY, yn);
            VS = fma2(xn, xn, VS); VS = fma2(yn, yn, VS);
            VXY = fma2(xn, yn, VXY);
            float vx0, vx1, vy0, vy1, vs0, vs1, vq0, vq1;
            unpack2(VX, vx0, vx1); unpack2(VY, vy0, vy1);
            unpack2(VS, vs0, vs1); unpack2(VXY, vq0, vq1);
            *(float4*)(sb + j * RSX + sidx)          = make_float4(vx0, vy0, vx1, vy1);
            *(float4*)(sb + PLANEQ + j * RSX + sidx) = make_float4(vs0, vq0, vs1, vq1);
            // evict oldest row (L1/L2-hit reload)
            u64 xo = *(const u64*)(xp + (size_t)r * IW + c);
            u64 yo = *(const u64*)(yp + (size_t)r * IW + c);
            u64 nxo = mul2(xo, NEG1X2), nyo = mul2(yo, NEG1X2);
            VX = add2(VX, nxo); VY = add2(VY, nyo);
            VS = fma2(nxo, xo, VS); VS = fma2(nyo, yo, VS);
            VXY = fma2(nxo, yo, VXY);
        }
    }
}

// Horizontal: 8 outputs (1 row x 8 cols) via conflict-free LDS.128 window.
template <bool GUARD>
__device__ __forceinline__ void horiz8(
    const float2* __restrict__ sb, int rb, int rmax,
    int jrow, int g, float& acc) {
    if (GUARD && rb + jrow > rmax) return;
    const float2* rowA = sb + jrow * RSX + 10 * g;
    const float2* rowB = rowA + PLANEQ;
    const int ofs2 = (g < 63) ? 5 : 1;   // g=63 overflow -> safe garbage, discarded

    u64 wa[14];
    {
        const ulonglong2* p = (const ulonglong2*)rowA;
#pragma unroll
        for (int i = 0; i < 4; ++i) { ulonglong2 t = p[i];        wa[2*i]   = t.x; wa[2*i+1] = t.y; }
#pragma unroll
        for (int i = 0; i < 3; ++i) { ulonglong2 t = p[ofs2 + i]; wa[8+2*i] = t.x; wa[9+2*i] = t.y; }
    }
    u64 Bout[8];
    {
        u64 B = wa[0];
#pragma unroll
        for (int k = 1; k < 7; ++k) B = add2(B, wa[k]);
        Bout[0] = B;
#pragma unroll
        for (int i = 1; i < 8; ++i) {
            B = add2(B, wa[i + 6]);
            B = fma2(wa[i - 1], NEG1X2, B);
            Bout[i] = B;
        }
    }
    u64 wb[14];
    {
        const ulonglong2* p = (const ulonglong2*)rowB;
#pragma unroll
        for (int i = 0; i < 4; ++i) { ulonglong2 t = p[i];        wb[2*i]   = t.x; wb[2*i+1] = t.y; }
#pragma unroll
        for (int i = 0; i < 3; ++i) { ulonglong2 t = p[ofs2 + i]; wb[8+2*i] = t.x; wb[9+2*i] = t.y; }
    }
    const int T = (OW - 8 * g < 8) ? (OW - 8 * g) : 8;
    u64 B = wb[0];
#pragma unroll
    for (int k = 1; k < 7; ++k) B = add2(B, wb[k]);
    {
        float sx, sy, ss, sxy;
        unpack2(Bout[0], sx, sy); unpack2(B, ss, sxy);
        acc += ssim_term(sx, sy, ss, sxy);
    }
#pragma unroll
    for (int i = 1; i < 8; ++i) {
        B = add2(B, wb[i + 6]);
        B = fma2(wb[i - 1], NEG1X2, B);
        if (i < T) {
            float sx, sy, ss, sxy;
            unpack2(Bout[i], sx, sy); unpack2(B, ss, sxy);
            acc += ssim_term(sx, sy, ss, sxy);
        }
    }
}

template <bool GUARD>
__device__ __forceinline__ float band_loop(
    const float* __restrict__ xp, const float* __restrict__ yp,
    float2* __restrict__ sm, int r0, int rmax, int tid) {

    const int c    = 2 * tid;                         // column pair
    const int sidx = 10 * (tid >> 2) + 2 * (tid & 3); // f2 index in padded row
    const int jrow = tid >> 6;                        // 0..3
    const int g    = tid & 63;                        // 0..63

    u64 VX = 0, VY = 0, VS = 0, VXY = 0;
    // prologue rows r0..r0+5 (always in-bounds)
#pragma unroll
    for (int k = 0; k < 6; ++k) {
        u64 x = *(const u64*)(xp + (size_t)(r0 + k) * IW + c);
        u64 y = *(const u64*)(yp + (size_t)(r0 + k) * IW + c);
        VX = add2(VX, x); VY = add2(VY, y);
        VS = fma2(x, x, VS); VS = fma2(y, y, VS);
        VXY = fma2(x, y, VXY);
    }

    const int nsub = GUARD ? (((rmax - r0) >> 2) + 1) : (BR / 4);
    float acc = 0.f;

    // subchunk 0
    {
        u64 nx[4], ny[4];
        prefetch4<false>(xp, yp, nx, ny, r0, rmax, c);
        vert4<false>(VX, VY, VS, VXY, sm, nx, ny, xp, yp, r0, rmax, c, sidx);
    }
    __syncthreads();

    for (int t = 0; t + 1 < nsub; t += 2) {
        {
            const int rbn = r0 + (t + 1) * 4;
            u64 nx[4], ny[4];
            prefetch4<GUARD>(xp, yp, nx, ny, rbn, rmax, c);
            horiz8<GUARD>(sm + (size_t)(t & 1) * BUFQ, r0 + t * 4, rmax, jrow, g, acc);
            vert4<GUARD>(VX, VY, VS, VXY, sm + (size_t)((t + 1) & 1) * BUFQ,
                         nx, ny, xp, yp, rbn, rmax, c, sidx);
            __syncthreads();
        }
        if (t + 2 < nsub) {
            const int rbn = r0 + (t + 2) * 4;
            u64 nx[4], ny[4];
            prefetch4<GUARD>(xp, yp, nx, ny, rbn, rmax, c);
            horiz8<GUARD>(sm + (size_t)((t + 1) & 1) * BUFQ, r0 + (t + 1) * 4, rmax, jrow, g, acc);
            vert4<GUARD>(VX, VY, VS, VXY, sm + (size_t)((t + 2) & 1) * BUFQ,
                         nx, ny, xp, yp, rbn, rmax, c, sidx);
            __syncthreads();
        }
    }
    horiz8<GUARD>(sm + (size_t)((nsub - 1) & 1) * BUFQ, r0 + (nsub - 1) * 4,
                  rmax, jrow, g, acc);
    return acc;
}

__global__ __launch_bounds__(256, 2)
void ssim_kernel(const float* __restrict__ X, const float* __restrict__ Y,
                 float* __restrict__ out) {
    extern __shared__ float2 smbuf[];
    __shared__ float wsum[8];
    __shared__ bool isLast;

    const int tid  = threadIdx.x;
    const int band = blockIdx.x;
    const int img  = blockIdx.y;

    const float* __restrict__ xp = X + (size_t)img * (512 * 512);
    const float* __restrict__ yp = Y + (size_t)img * (512 * 512);
    const int r0   = band * BR;
    const int rmax = min(r0 + BR - 1, OH - 1);

    float acc;
    if (rmax == r0 + BR - 1) {
        acc = band_loop<false>(xp, yp, smbuf, r0, rmax, tid);
    } else {
        acc = band_loop<true>(xp, yp, smbuf, r0, rmax, tid);
    }

    // ---- block reduction ----
#pragma unroll
    for (int o = 16; o > 0; o >>= 1)
        acc += __shfl_xor_sync(0xffffffffu, acc, o);
    if ((tid & 31) == 0) wsum[tid >> 5] = acc;
    __syncthreads();

    if (tid == 0) {
        float s = 0.f;
#pragma unroll
        for (int w = 0; w < 8; ++w) s += wsum[w];
        g_partials[img * NBANDS + band] = s;
        __threadfence();
        unsigned int old = atomicAdd(&g_count, 1u);
        isLast = (old == NCTA - 1);
    }
    __syncthreads();

    // ---- deterministic last-block global reduction ----
    if (isLast) {
        float s = 0.f;
        for (int i = tid; i < NCTA; i += 256) s += g_partials[i];
#pragma unroll
        for (int o = 16; o > 0; o >>= 1)
            s += __shfl_xor_sync(0xffffffffu, s, o);
        if ((tid & 31) == 0) wsum[tid >> 5] = s;
        __syncthreads();
        if (tid == 0) {
            float t = 0.f;
#pragma unroll
            for (int w = 0; w < 8; ++w) t += wsum[w];
            out[0] = 1.0f - t * (1.0f / 24579456.0f);  // 96*506*506
            g_count = 0;  // reset for next graph replay
        }
    }
}

extern "C" void kernel_launch(void* const* d_in, const int* in_sizes, int n_in,
                              void* d_out, int out_size) {
    (void)in_sizes; (void)n_in; (void)out_size;
    const float* X = (const float*)d_in[0];
    const float* Y = (const float*)d_in[1];

    cudaFuncSetAttribute(ssim_kernel,
                         cudaFuncAttributeMaxDynamicSharedMemorySize, SMEM_BYTES);

    dim3 grid(NBANDS, NIMG);
    ssim_kernel<<<grid, 256, SMEM_BYTES>>>(X, Y, (float*)d_out);
}

// round 8
// speedup vs baseline: 1.3410x; 1.0603x over previous
#include <cuda_runtime.h>

// SSIM loss, 7x7 valid window, [32,3,512,512] fp32, scalar out.
// R8 = R7 with the prologue ring-slot fix (rows r0..r0+5 -> slots 0..5,
// matching vert4's phase-0 subtraction order).
// R4 skeleton (512 thr, merged-phase double buffer, 4-row subchunks,
// register-ring vertical) + conflict-free padded-group horizontal:
// 4-col groups, 6 float2 stride (4 data + 2 pad) -> window = 5 LDS.128
// per plane per 4-output task.

#define IW     512
#define OH     506
#define OW     506
#define BR     88
#define NBANDS 6
#define NIMG   96
#define NCTA   (NBANDS * NIMG)      // 576
#define GS     6                    // float2 per group (4 data + 2 pad)
#define ROWF2  (128 * GS)           // 768 f2 per staged row
#define PLANEF2 (4 * ROWF2)         // 3072
#define BUFF2  (2 * PLANEF2)        // 6144
#define SMEM_F2 (2 * BUFF2 + 16)    // + tail pad for last-group halo reads
#define SMEM_BYTES (SMEM_F2 * 8)    // 98,432 B -> 2 CTAs/SM

typedef unsigned long long u64;

__device__ float g_partials[NCTA];
__device__ unsigned int g_count = 0;

__device__ __forceinline__ u64 add2(u64 a, u64 b) {
    u64 r; asm("add.rn.f32x2 %0, %1, %2;" : "=l"(r) : "l"(a), "l"(b)); return r;
}
__device__ __forceinline__ u64 fma2(u64 a, u64 b, u64 c) {
    u64 r; asm("fma.rn.f32x2 %0, %1, %2, %3;" : "=l"(r) : "l"(a), "l"(b), "l"(c)); return r;
}
__device__ __forceinline__ void unpack2(u64 v, float& a, float& b) {
    asm("mov.b64 {%0, %1}, %2;" : "=f"(a), "=f"(b) : "l"(v));
}
#define NEG1X2 0xBF800000BF800000ull

__device__ __forceinline__ float ssim_term(float sx, float sy, float ss, float sxy) {
    const float c1big = 0.2401f;   // 2401 * (0.01)^2
    const float c2big = 2.1168f;   // 2352 * (0.03)^2
    float t1 = sx * sy;
    float a1 = fmaf(t1, 2.0f, c1big);
    float b1 = fmaf(sx, sx, c1big);
    b1 = fmaf(sy, sy, b1);
    float a2 = fmaf(sxy, 98.0f, c2big);
    a2 = fmaf(t1, -2.0f, a2);
    float b2 = fmaf(ss, 49.0f, c2big);
    b2 = fmaf(sx, -sx, b2);
    b2 = fmaf(sy, -sy, b2);
    return __fdividef(a1 * a2, b1 * b2);
}

struct VState {
    float Vx, Vy, Vs, Vxy;
    float rx[8], ry[8];   // ring, static indices via template<PH>
};

template <bool GUARD>
__device__ __forceinline__ void prefetch4(
    const float* __restrict__ xp, const float* __restrict__ yp,
    float* nx, float* ny, int rbn, int rmax, int col) {
#pragma unroll
    for (int j = 0; j < 4; ++j) {
        if (!GUARD || rbn + j <= rmax) {
            nx[j] = xp[(size_t)(rbn + j + 6) * IW + col];
            ny[j] = yp[(size_t)(rbn + j + 6) * IW + col];
        }
    }
}

// Vertical: 4 rows (rb % 8 == PH), scalar per-column running sums, store to
// padded-group float2 layout. Ring invariant: before j, slot (PH+j)&7 holds
// row rb+j (the row leaving the 7-window); new row rb+j+6 replaces slot
// (PH+j+6)&7.
template <int PH, bool GUARD>
__device__ __forceinline__ void vert4(
    VState& v, float2* __restrict__ buf, const float* nx, const float* ny,
    int rb, int rmax, int sidx) {
#pragma unroll
    for (int j = 0; j < 4; ++j) {
        if (!GUARD || rb + j <= rmax) {
            float xn = nx[j], yn = ny[j];
            v.Vx += xn; v.Vy += yn;
            v.Vs  = fmaf(xn, xn, v.Vs);
            v.Vs  = fmaf(yn, yn, v.Vs);
            v.Vxy = fmaf(xn, yn, v.Vxy);
            buf[j * ROWF2 + sidx]           = make_float2(v.Vx, v.Vy);
            buf[PLANEF2 + j * ROWF2 + sidx] = make_float2(v.Vs, v.Vxy);
            float xo = v.rx[(PH + j) & 7];
            float yo = v.ry[(PH + j) & 7];
            v.Vx -= xo; v.Vy -= yo;
            v.Vs  = fmaf(xo, -xo, v.Vs);
            v.Vs  = fmaf(yo, -yo, v.Vs);
            v.Vxy = fmaf(xo, -yo, v.Vxy);
            v.rx[(PH + j + 6) & 7] = xn;
            v.ry[(PH + j + 6) & 7] = yn;
        }
    }
}

// Horizontal: 4 outputs (1 row x 4 cols) via 5 conflict-free LDS.128/plane.
// f4 offsets {0,1,3,4,6} from group base give f2 (column) indices
// {0,1,2,3, 6,7,8,9, 12,13} == columns 4g..4g+9 across padded groups.
__device__ __forceinline__ void load_win(const ulonglong2* __restrict__ p, u64* w) {
    ulonglong2 t0 = p[0], t1 = p[1], t2 = p[3], t3 = p[4], t4 = p[6];
    w[0] = t0.x; w[1] = t0.y; w[2] = t1.x; w[3] = t1.y;
    w[4] = t2.x; w[5] = t2.y; w[6] = t3.x; w[7] = t3.y;
    w[8] = t4.x; w[9] = t4.y;
}

template <bool GUARD>
__device__ __forceinline__ void horiz4(
    const float2* __restrict__ sb, int rb, int rmax,
    int jrow, int g, float& acc) {
    const int c0 = 4 * g;
    if (c0 >= OW) return;                 // g == 127
    if (GUARD && rb + jrow > rmax) return;

    const ulonglong2* pA =
        (const ulonglong2*)(sb + jrow * ROWF2 + GS * g);
    const ulonglong2* pB =
        (const ulonglong2*)(sb + PLANEF2 + jrow * ROWF2 + GS * g);

    u64 w[10];
    load_win(pA, w);
    u64 Bout[4];
    {
        u64 B = w[0];
#pragma unroll
        for (int k = 1; k < 7; ++k) B = add2(B, w[k]);
        Bout[0] = B;
#pragma unroll
        for (int i = 1; i < 4; ++i) {
            B = add2(B, w[i + 6]);
            B = fma2(w[i - 1], NEG1X2, B);
            Bout[i] = B;
        }
    }
    load_win(pB, w);
    const int T = (OW - c0 < 4) ? (OW - c0) : 4;
    u64 B = w[0];
#pragma unroll
    for (int k = 1; k < 7; ++k) B = add2(B, w[k]);
    {
        float sx, sy, ss, sxy;
        unpack2(Bout[0], sx, sy); unpack2(B, ss, sxy);
        acc += ssim_term(sx, sy, ss, sxy);
    }
#pragma unroll
    for (int i = 1; i < 4; ++i) {
        B = add2(B, w[i + 6]);
        B = fma2(w[i - 1], NEG1X2, B);
        if (i < T) {
            float sx, sy, ss, sxy;
            unpack2(Bout[i], sx, sy); unpack2(B, ss, sxy);
            acc += ssim_term(sx, sy, ss, sxy);
        }
    }
}

template <bool GUARD>
__device__ __forceinline__ float band_loop(
    const float* __restrict__ xp, const float* __restrict__ yp,
    float2* __restrict__ sm, int r0, int rmax, int tid) {

    const int col  = tid;
    const int sidx = GS * (tid >> 2) + (tid & 3);  // f2 store index in row
    const int jrow = tid >> 7;                     // 0..3
    const int g    = tid & 127;                    // 0..127

    VState v;
    v.Vx = 0.f; v.Vy = 0.f; v.Vs = 0.f; v.Vxy = 0.f;

    // prologue: rows r0..r0+5 -> ring slots 0..5 (phase-0 convention)
#pragma unroll
    for (int k = 0; k < 6; ++k) {
        float x = xp[(size_t)(r0 + k) * IW + col];
        float y = yp[(size_t)(r0 + k) * IW + col];
        v.Vx += x; v.Vy += y;
        v.Vs  = fmaf(x, x, v.Vs);
        v.Vs  = fmaf(y, y, v.Vs);
        v.Vxy = fmaf(x, y, v.Vxy);
        v.rx[k] = x; v.ry[k] = y;
    }

    const int nsub = GUARD ? (((rmax - r0) >> 2) + 1) : (BR / 4);
    float acc = 0.f;

    // subchunk 0 (rows r0..r0+3, always valid)
    {
        float nx[4], ny[4];
        prefetch4<false>(xp, yp, nx, ny, r0, rmax, col);
        vert4<0, false>(v, sm, nx, ny, r0, rmax, sidx);
    }
    __syncthreads();

    for (int t = 0; t + 1 < nsub; t += 2) {
        {   // horizontal(t) + vertical(t+1), rb_next % 8 == 4
            const int rbn = r0 + (t + 1) * 4;
            float nx[4], ny[4];
            prefetch4<GUARD>(xp, yp, nx, ny, rbn, rmax, col);
            horiz4<GUARD>(sm + (size_t)(t & 1) * BUFF2, r0 + t * 4, rmax, jrow, g, acc);
            vert4<4, GUARD>(v, sm + (size_t)((t + 1) & 1) * BUFF2,
                            nx, ny, rbn, rmax, sidx);
            __syncthreads();
        }
        if (t + 2 < nsub) {   // horizontal(t+1) + vertical(t+2), rb_next % 8 == 0
            const int rbn = r0 + (t + 2) * 4;
            float nx[4], ny[4];
            prefetch4<GUARD>(xp, yp, nx, ny, rbn, rmax, col);
            horiz4<GUARD>(sm + (size_t)((t + 1) & 1) * BUFF2, r0 + (t + 1) * 4,
                          rmax, jrow, g, acc);
            vert4<0, GUARD>(v, sm + (size_t)((t + 2) & 1) * BUFF2,
                            nx, ny, rbn, rmax, sidx);
            __syncthreads();
        }
    }
    horiz4<GUARD>(sm + (size_t)((nsub - 1) & 1) * BUFF2, r0 + (nsub - 1) * 4,
                  rmax, jrow, g, acc);
    return acc;
}

__global__ __launch_bounds__(512, 2)
void ssim_kernel(const float* __restrict__ X, const float* __restrict__ Y,
                 float* __restrict__ out) {
    extern __shared__ float2 smbuf[];
    __shared__ float wsum[16];
    __shared__ bool isLast;

    const int tid  = threadIdx.x;
    const int band = blockIdx.x;
    const int img  = blockIdx.y;

    const float* __restrict__ xp = X + (size_t)img * (512 * 512);
    const float* __restrict__ yp = Y + (size_t)img * (512 * 512);
    const int r0   = band * BR;
    const int rmax = min(r0 + BR - 1, OH - 1);

    float acc;
    if (rmax == r0 + BR - 1) {
        acc = band_loop<false>(xp, yp, smbuf, r0, rmax, tid);
    } else {
        acc = band_loop<true>(xp, yp, smbuf, r0, rmax, tid);
    }

    // ---- block reduction ----
#pragma unroll
    for (int o = 16; o > 0; o >>= 1)
        acc += __shfl_xor_sync(0xffffffffu, acc, o);
    if ((tid & 31) == 0) wsum[tid >> 5] = acc;
    __syncthreads();

    if (tid == 0) {
        float s = 0.f;
#pragma unroll
        for (int w = 0; w < 16; ++w) s += wsum[w];
        g_partials[img * NBANDS + band] = s;
        __threadfence();
        unsigned int old = atomicAdd(&g_count, 1u);
        isLast = (old == NCTA - 1);
    }
    __syncthreads();

    // ---- deterministic last-block global reduction ----
    if (isLast) {
        float s = 0.f;
        for (int i = tid; i < NCTA; i += 512) s += g_partials[i];
#pragma unroll
        for (int o = 16; o > 0; o >>= 1)
            s += __shfl_xor_sync(0xffffffffu, s, o);
        if ((tid & 31) == 0) wsum[tid >> 5] = s;
        __syncthreads();
        if (tid == 0) {
            float t = 0.f;
#pragma unroll
            for (int w = 0; w < 16; ++w) t += wsum[w];
            out[0] = 1.0f - t * (1.0f / 24579456.0f);  // 96*506*506
            g_count = 0;  // reset for next graph replay
        }
    }
}

extern "C" void kernel_launch(void* const* d_in, const int* in_sizes, int n_in,
                              void* d_out, int out_size) {
    (void)in_sizes; (void)n_in; (void)out_size;
    const float* X = (const float*)d_in[0];
    const float* Y = (const float*)d_in[1];

    cudaFuncSetAttribute(ssim_kernel,
                         cudaFuncAttributeMaxDynamicSharedMemorySize, SMEM_BYTES);

    dim3 grid(NBANDS, NIMG);
    ssim_kernel<<<grid, 512, SMEM_BYTES>>>(X, Y, (float*)d_out);
}

// round 9
// speedup vs baseline: 1.4211x; 1.0597x over previous
#include <cuda_runtime.h>

// SSIM loss, 7x7 valid window, [32,3,512,512] fp32, scalar out.
// R9 = R8 + conflict-free STS: within each warp, half-warp 0 stores even
// groups {0,2,4,6}, half-warp 1 odd groups {1,3,5,7} (group bank-stride 12
// -> even-q ranges partition the 32 banks). LDG stays coalesced under the
// intra-warp column permutation. Everything else identical to R8.

#define IW     512
#define OH     506
#define OW     506
#define BR     88
#define NBANDS 6
#define NIMG   96
#define NCTA   (NBANDS * NIMG)      // 576
#define GS     6                    // float2 per group (4 data + 2 pad)
#define ROWF2  (128 * GS)           // 768 f2 per staged row
#define PLANEF2 (4 * ROWF2)         // 3072
#define BUFF2  (2 * PLANEF2)        // 6144
#define SMEM_F2 (2 * BUFF2 + 16)    // + tail pad for last-group halo reads
#define SMEM_BYTES (SMEM_F2 * 8)    // 98,432 B -> 2 CTAs/SM

typedef unsigned long long u64;

__device__ float g_partials[NCTA];
__device__ unsigned int g_count = 0;

__device__ __forceinline__ u64 add2(u64 a, u64 b) {
    u64 r; asm("add.rn.f32x2 %0, %1, %2;" : "=l"(r) : "l"(a), "l"(b)); return r;
}
__device__ __forceinline__ u64 fma2(u64 a, u64 b, u64 c) {
    u64 r; asm("fma.rn.f32x2 %0, %1, %2, %3;" : "=l"(r) : "l"(a), "l"(b), "l"(c)); return r;
}
__device__ __forceinline__ void unpack2(u64 v, float& a, float& b) {
    asm("mov.b64 {%0, %1}, %2;" : "=f"(a), "=f"(b) : "l"(v));
}
#define NEG1X2 0xBF800000BF800000ull

__device__ __forceinline__ float ssim_term(float sx, float sy, float ss, float sxy) {
    const float c1big = 0.2401f;   // 2401 * (0.01)^2
    const float c2big = 2.1168f;   // 2352 * (0.03)^2
    float t1 = sx * sy;
    float a1 = fmaf(t1, 2.0f, c1big);
    float b1 = fmaf(sx, sx, c1big);
    b1 = fmaf(sy, sy, b1);
    float a2 = fmaf(sxy, 98.0f, c2big);
    a2 = fmaf(t1, -2.0f, a2);
    float b2 = fmaf(ss, 49.0f, c2big);
    b2 = fmaf(sx, -sx, b2);
    b2 = fmaf(sy, -sy, b2);
    return __fdividef(a1 * a2, b1 * b2);
}

struct VState {
    float Vx, Vy, Vs, Vxy;
    float rx[8], ry[8];   // ring, static indices via template<PH>
};

template <bool GUARD>
__device__ __forceinline__ void prefetch4(
    const float* __restrict__ xp, const float* __restrict__ yp,
    float* nx, float* ny, int rbn, int rmax, int col) {
#pragma unroll
    for (int j = 0; j < 4; ++j) {
        if (!GUARD || rbn + j <= rmax) {
            nx[j] = xp[(size_t)(rbn + j + 6) * IW + col];
            ny[j] = yp[(size_t)(rbn + j + 6) * IW + col];
        }
    }
}

// Vertical: 4 rows (rb % 8 == PH), per-column running sums, store to padded
// group layout. Ring: slot (PH+j)&7 holds the departing row rb+j; new row
// rb+j+6 replaces slot (PH+j+6)&7.
template <int PH, bool GUARD>
__device__ __forceinline__ void vert4(
    VState& v, float2* __restrict__ buf, const float* nx, const float* ny,
    int rb, int rmax, int sidx) {
#pragma unroll
    for (int j = 0; j < 4; ++j) {
        if (!GUARD || rb + j <= rmax) {
            float xn = nx[j], yn = ny[j];
            v.Vx += xn; v.Vy += yn;
            v.Vs  = fmaf(xn, xn, v.Vs);
            v.Vs  = fmaf(yn, yn, v.Vs);
            v.Vxy = fmaf(xn, yn, v.Vxy);
            buf[j * ROWF2 + sidx]           = make_float2(v.Vx, v.Vy);
            buf[PLANEF2 + j * ROWF2 + sidx] = make_float2(v.Vs, v.Vxy);
            float xo = v.rx[(PH + j) & 7];
            float yo = v.ry[(PH + j) & 7];
            v.Vx -= xo; v.Vy -= yo;
            v.Vs  = fmaf(xo, -xo, v.Vs);
            v.Vs  = fmaf(yo, -yo, v.Vs);
            v.Vxy = fmaf(xo, -yo, v.Vxy);
            v.rx[(PH + j + 6) & 7] = xn;
            v.ry[(PH + j + 6) & 7] = yn;
        }
    }
}

// Horizontal: 4 outputs via 5 conflict-free LDS.128 per plane.
__device__ __forceinline__ void load_win(const ulonglong2* __restrict__ p, u64* w) {
    ulonglong2 t0 = p[0], t1 = p[1], t2 = p[3], t3 = p[4], t4 = p[6];
    w[0] = t0.x; w[1] = t0.y; w[2] = t1.x; w[3] = t1.y;
    w[4] = t2.x; w[5] = t2.y; w[6] = t3.x; w[7] = t3.y;
    w[8] = t4.x; w[9] = t4.y;
}

template <bool GUARD>
__device__ __forceinline__ void horiz4(
    const float2* __restrict__ sb, int rb, int rmax,
    int jrow, int g, float& acc) {
    const int c0 = 4 * g;
    if (c0 >= OW) return;                 // g == 127
    if (GUARD && rb + jrow > rmax) return;

    const ulonglong2* pA =
        (const ulonglong2*)(sb + jrow * ROWF2 + GS * g);
    const ulonglong2* pB =
        (const ulonglong2*)(sb + PLANEF2 + jrow * ROWF2 + GS * g);

    u64 w[10];
    load_win(pA, w);
    u64 Bout[4];
    {
        u64 B = w[0];
#pragma unroll
        for (int k = 1; k < 7; ++k) B = add2(B, w[k]);
        Bout[0] = B;
#pragma unroll
        for (int i = 1; i < 4; ++i) {
            B = add2(B, w[i + 6]);
            B = fma2(w[i - 1], NEG1X2, B);
            Bout[i] = B;
        }
    }
    load_win(pB, w);
    const int T = (OW - c0 < 4) ? (OW - c0) : 4;
    u64 B = w[0];
#pragma unroll
    for (int k = 1; k < 7; ++k) B = add2(B, w[k]);
    {
        float sx, sy, ss, sxy;
        unpack2(Bout[0], sx, sy); unpack2(B, ss, sxy);
        acc += ssim_term(sx, sy, ss, sxy);
    }
#pragma unroll
    for (int i = 1; i < 4; ++i) {
        B = add2(B, w[i + 6]);
        B = fma2(w[i - 1], NEG1X2, B);
        if (i < T) {
            float sx, sy, ss, sxy;
            unpack2(Bout[i], sx, sy); unpack2(B, ss, sxy);
            acc += ssim_term(sx, sy, ss, sxy);
        }
    }
}

template <bool GUARD>
__device__ __forceinline__ float band_loop(
    const float* __restrict__ xp, const float* __restrict__ yp,
    float2* __restrict__ sm, int r0, int rmax, int tid) {

    // Conflict-free store permutation: half-warp 0 -> even groups, 1 -> odd.
    const int lane = tid & 31;
    const int warp = tid >> 5;
    const int q    = (((lane & 15) >> 2) << 1) | (lane >> 4);  // 0,2,4,6 / 1,3,5,7
    const int r_   = lane & 3;
    const int col  = warp * 32 + q * 4 + r_;
    const int sidx = GS * (warp * 8 + q) + r_;     // f2 store index in row

    const int jrow = tid >> 7;                     // 0..3
    const int g    = tid & 127;                    // 0..127

    VState v;
    v.Vx = 0.f; v.Vy = 0.f; v.Vs = 0.f; v.Vxy = 0.f;

    // prologue: rows r0..r0+5 -> ring slots 0..5
#pragma unroll
    for (int k = 0; k < 6; ++k) {
        float x = xp[(size_t)(r0 + k) * IW + col];
        float y = yp[(size_t)(r0 + k) * IW + col];
        v.Vx += x; v.Vy += y;
        v.Vs  = fmaf(x, x, v.Vs);
        v.Vs  = fmaf(y, y, v.Vs);
        v.Vxy = fmaf(x, y, v.Vxy);
        v.rx[k] = x; v.ry[k] = y;
    }

    const int nsub = GUARD ? (((rmax - r0) >> 2) + 1) : (BR / 4);
    float acc = 0.f;

    // subchunk 0 (rows r0..r0+3, always valid)
    {
        float nx[4], ny[4];
        prefetch4<false>(xp, yp, nx, ny, r0, rmax, col);
        vert4<0, false>(v, sm, nx, ny, r0, rmax, sidx);
    }
    __syncthreads();

    for (int t = 0; t + 1 < nsub; t += 2) {
        {   // horizontal(t) + vertical(t+1), rb_next % 8 == 4
            const int rbn = r0 + (t + 1) * 4;
            float nx[4], ny[4];
            prefetch4<GUARD>(xp, yp, nx, ny, rbn, rmax, col);
            horiz4<GUARD>(sm + (size_t)(t & 1) * BUFF2, r0 + t * 4, rmax, jrow, g, acc);
            vert4<4, GUARD>(v, sm + (size_t)((t + 1) & 1) * BUFF2,
                            nx, ny, rbn, rmax, sidx);
            __syncthreads();
        }
        if (t + 2 < nsub) {   // horizontal(t+1) + vertical(t+2), rb_next % 8 == 0
            const int rbn = r0 + (t + 2) * 4;
            float nx[4], ny[4];
            prefetch4<GUARD>(xp, yp, nx, ny, rbn, rmax, col);
            horiz4<GUARD>(sm + (size_t)((t + 1) & 1) * BUFF2, r0 + (t + 1) * 4,
                          rmax, jrow, g, acc);
            vert4<0, GUARD>(v, sm + (size_t)((t + 2) & 1) * BUFF2,
                            nx, ny, rbn, rmax, sidx);
            __syncthreads();
        }
    }
    horiz4<GUARD>(sm + (size_t)((nsub - 1) & 1) * BUFF2, r0 + (nsub - 1) * 4,
                  rmax, jrow, g, acc);
    return acc;
}

__global__ __launch_bounds__(512, 2)
void ssim_kernel(const float* __restrict__ X, const float* __restrict__ Y,
                 float* __restrict__ out) {
    extern __shared__ float2 smbuf[];
    __shared__ float wsum[16];
    __shared__ bool isLast;

    const int tid  = threadIdx.x;
    const int band = blockIdx.x;
    const int img  = blockIdx.y;

    const float* __restrict__ xp = X + (size_t)img * (512 * 512);
    const float* __restrict__ yp = Y + (size_t)img * (512 * 512);
    const int r0   = band * BR;
    const int rmax = min(r0 + BR - 1, OH - 1);

    float acc;
    if (rmax == r0 + BR - 1) {
        acc = band_loop<false>(xp, yp, smbuf, r0, rmax, tid);
    } else {
        acc = band_loop<true>(xp, yp, smbuf, r0, rmax, tid);
    }

    // ---- block reduction ----
#pragma unroll
    for (int o = 16; o > 0; o >>= 1)
        acc += __shfl_xor_sync(0xffffffffu, acc, o);
    if ((tid & 31) == 0) wsum[tid >> 5] = acc;
    __syncthreads();

    if (tid == 0) {
        float s = 0.f;
#pragma unroll
        for (int w = 0; w < 16; ++w) s += wsum[w];
        g_partials[img * NBANDS + band] = s;
        __threadfence();
        unsigned int old = atomicAdd(&g_count, 1u);
        isLast = (old == NCTA - 1);
    }
    __syncthreads();

    // ---- deterministic last-block global reduction ----
    if (isLast) {
        float s = 0.f;
        for (int i = tid; i < NCTA; i += 512) s += g_partials[i];
#pragma unroll
        for (int o = 16; o > 0; o >>= 1)
            s += __shfl_xor_sync(0xffffffffu, s, o);
        if ((tid & 31) == 0) wsum[tid >> 5] = s;
        __syncthreads();
        if (tid == 0) {
            float t = 0.f;
#pragma unroll
            for (int w = 0; w < 16; ++w) t += wsum[w];
            out[0] = 1.0f - t * (1.0f / 24579456.0f);  // 96*506*506
            g_count = 0;  // reset for next graph replay
        }
    }
}

extern "C" void kernel_launch(void* const* d_in, const int* in_sizes, int n_in,
                              void* d_out, int out_size) {
    (void)in_sizes; (void)n_in; (void)out_size;
    const float* X = (const float*)d_in[0];
    const float* Y = (const float*)d_in[1];

    cudaFuncSetAttribute(ssim_kernel,
                         cudaFuncAttributeMaxDynamicSharedMemorySize, SMEM_BYTES);

    dim3 grid(NBANDS, NIMG);
    ssim_kernel<<<grid, 512, SMEM_BYTES>>>(X, Y, (float*)d_out);
}

// round 10
// speedup vs baseline: 1.4257x; 1.0033x over previous
#include <cuda_runtime.h>

// SSIM loss, 7x7 valid window, [32,3,512,512] fp32, scalar out.
// R9 = R8 + conflict-free STS: within each warp, half-warp 0 stores even
// groups {0,2,4,6}, half-warp 1 odd groups {1,3,5,7} (group bank-stride 12
// -> even-q ranges partition the 32 banks). LDG stays coalesced under the
// intra-warp column permutation. Everything else identical to R8.

#define IW     512
#define OH     506
#define OW     506
#define BR     88
#define NBANDS 6
#define NIMG   96
#define NCTA   (NBANDS * NIMG)      // 576
#define GS     6                    // float2 per group (4 data + 2 pad)
#define ROWF2  (128 * GS)           // 768 f2 per staged row
#define PLANEF2 (4 * ROWF2)         // 3072
#define BUFF2  (2 * PLANEF2)        // 6144
#define SMEM_F2 (2 * BUFF2 + 16)    // + tail pad for last-group halo reads
#define SMEM_BYTES (SMEM_F2 * 8)    // 98,432 B -> 2 CTAs/SM

typedef unsigned long long u64;

__device__ float g_partials[NCTA];
__device__ unsigned int g_count = 0;

__device__ __forceinline__ u64 add2(u64 a, u64 b) {
    u64 r; asm("add.rn.f32x2 %0, %1, %2;" : "=l"(r) : "l"(a), "l"(b)); return r;
}
__device__ __forceinline__ u64 fma2(u64 a, u64 b, u64 c) {
    u64 r; asm("fma.rn.f32x2 %0, %1, %2, %3;" : "=l"(r) : "l"(a), "l"(b), "l"(c)); return r;
}
__device__ __forceinline__ void unpack2(u64 v, float& a, float& b) {
    asm("mov.b64 {%0, %1}, %2;" : "=f"(a), "=f"(b) : "l"(v));
}
#define NEG1X2 0xBF800000BF800000ull

__device__ __forceinline__ float ssim_term(float sx, float sy, float ss, float sxy) {
    const float c1big = 0.2401f;   // 2401 * (0.01)^2
    const float c2big = 2.1168f;   // 2352 * (0.03)^2
    float t1 = sx * sy;
    float a1 = fmaf(t1, 2.0f, c1big);
    float b1 = fmaf(sx, sx, c1big);
    b1 = fmaf(sy, sy, b1);
    float a2 = fmaf(sxy, 98.0f, c2big);
    a2 = fmaf(t1, -2.0f, a2);
    float b2 = fmaf(ss, 49.0f, c2big);
    b2 = fmaf(sx, -sx, b2);
    b2 = fmaf(sy, -sy, b2);
    return __fdividef(a1 * a2, b1 * b2);
}

struct VState {
    float Vx, Vy, Vs, Vxy;
    float rx[8], ry[8];   // ring, static indices via template<PH>
};

template <bool GUARD>
__device__ __forceinline__ void prefetch4(
    const float* __restrict__ xp, const float* __restrict__ yp,
    float* nx, float* ny, int rbn, int rmax, int col) {
#pragma unroll
    for (int j = 0; j < 4; ++j) {
        if (!GUARD || rbn + j <= rmax) {
            nx[j] = xp[(size_t)(rbn + j + 6) * IW + col];
            ny[j] = yp[(size_t)(rbn + j + 6) * IW + col];
        }
    }
}

// Vertical: 4 rows (rb % 8 == PH), per-column running sums, store to padded
// group layout. Ring: slot (PH+j)&7 holds the departing row rb+j; new row
// rb+j+6 replaces slot (PH+j+6)&7.
template <int PH, bool GUARD>
__device__ __forceinline__ void vert4(
    VState& v, float2* __restrict__ buf, const float* nx, const float* ny,
    int rb, int rmax, int sidx) {
#pragma unroll
    for (int j = 0; j < 4; ++j) {
        if (!GUARD || rb + j <= rmax) {
            float xn = nx[j], yn = ny[j];
            v.Vx += xn; v.Vy += yn;
            v.Vs  = fmaf(xn, xn, v.Vs);
            v.Vs  = fmaf(yn, yn, v.Vs);
            v.Vxy = fmaf(xn, yn, v.Vxy);
            buf[j * ROWF2 + sidx]           = make_float2(v.Vx, v.Vy);
            buf[PLANEF2 + j * ROWF2 + sidx] = make_float2(v.Vs, v.Vxy);
            float xo = v.rx[(PH + j) & 7];
            float yo = v.ry[(PH + j) & 7];
            v.Vx -= xo; v.Vy -= yo;
            v.Vs  = fmaf(xo, -xo, v.Vs);
            v.Vs  = fmaf(yo, -yo, v.Vs);
            v.Vxy = fmaf(xo, -yo, v.Vxy);
            v.rx[(PH + j + 6) & 7] = xn;
            v.ry[(PH + j + 6) & 7] = yn;
        }
    }
}

// Horizontal: 4 outputs via 5 conflict-free LDS.128 per plane.
__device__ __forceinline__ void load_win(const ulonglong2* __restrict__ p, u64* w) {
    ulonglong2 t0 = p[0], t1 = p[1], t2 = p[3], t3 = p[4], t4 = p[6];
    w[0] = t0.x; w[1] = t0.y; w[2] = t1.x; w[3] = t1.y;
    w[4] = t2.x; w[5] = t2.y; w[6] = t3.x; w[7] = t3.y;
    w[8] = t4.x; w[9] = t4.y;
}

template <bool GUARD>
__device__ __forceinline__ void horiz4(
    const float2* __restrict__ sb, int rb, int rmax,
    int jrow, int g, float& acc) {
    const int c0 = 4 * g;
    if (c0 >= OW) return;                 // g == 127
    if (GUARD && rb + jrow > rmax) return;

    const ulonglong2* pA =
        (const ulonglong2*)(sb + jrow * ROWF2 + GS * g);
    const ulonglong2* pB =
        (const ulonglong2*)(sb + PLANEF2 + jrow * ROWF2 + GS * g);

    u64 w[10];
    load_win(pA, w);
    u64 Bout[4];
    {
        u64 B = w[0];
#pragma unroll
        for (int k = 1; k < 7; ++k) B = add2(B, w[k]);
        Bout[0] = B;
#pragma unroll
        for (int i = 1; i < 4; ++i) {
            B = add2(B, w[i + 6]);
            B = fma2(w[i - 1], NEG1X2, B);
            Bout[i] = B;
        }
    }
    load_win(pB, w);
    const int T = (OW - c0 < 4) ? (OW - c0) : 4;
    u64 B = w[0];
#pragma unroll
    for (int k = 1; k < 7; ++k) B = add2(B, w[k]);
    {
        float sx, sy, ss, sxy;
        unpack2(Bout[0], sx, sy); unpack2(B, ss, sxy);
        acc += ssim_term(sx, sy, ss, sxy);
    }
#pragma unroll
    for (int i = 1; i < 4; ++i) {
        B = add2(B, w[i + 6]);
        B = fma2(w[i - 1], NEG1X2, B);
        if (i < T) {
            float sx, sy, ss, sxy;
            unpack2(Bout[i], sx, sy); unpack2(B, ss, sxy);
            acc += ssim_term(sx, sy, ss, sxy);
        }
    }
}

template <bool GUARD>
__device__ __forceinline__ float band_loop(
    const float* __restrict__ xp, const float* __restrict__ yp,
    float2* __restrict__ sm, int r0, int rmax, int tid) {

    // Conflict-free store permutation: half-warp 0 -> even groups, 1 -> odd.
    const int lane = tid & 31;
    const int warp = tid >> 5;
    const int q    = (((lane & 15) >> 2) << 1) | (lane >> 4);  // 0,2,4,6 / 1,3,5,7
    const int r_   = lane & 3;
    const int col  = warp * 32 + q * 4 + r_;
    const int sidx = GS * (warp * 8 + q) + r_;     // f2 store index in row

    const int jrow = tid >> 7;                     // 0..3
    const int g    = tid & 127;                    // 0..127

    VState v;
    v.Vx = 0.f; v.Vy = 0.f; v.Vs = 0.f; v.Vxy = 0.f;

    // prologue: rows r0..r0+5 -> ring slots 0..5
#pragma unroll
    for (int k = 0; k < 6; ++k) {
        float x = xp[(size_t)(r0 + k) * IW + col];
        float y = yp[(size_t)(r0 + k) * IW + col];
        v.Vx += x; v.Vy += y;
        v.Vs  = fmaf(x, x, v.Vs);
        v.Vs  = fmaf(y, y, v.Vs);
        v.Vxy = fmaf(x, y, v.Vxy);
        v.rx[k] = x; v.ry[k] = y;
    }

    const int nsub = GUARD ? (((rmax - r0) >> 2) + 1) : (BR / 4);
    float acc = 0.f;

    // subchunk 0 (rows r0..r0+3, always valid)
    {
        float nx[4], ny[4];
        prefetch4<false>(xp, yp, nx, ny, r0, rmax, col);
        vert4<0, false>(v, sm, nx, ny, r0, rmax, sidx);
    }
    __syncthreads();

    for (int t = 0; t + 1 < nsub; t += 2) {
        {   // horizontal(t) + vertical(t+1), rb_next % 8 == 4
            const int rbn = r0 + (t + 1) * 4;
            float nx[4], ny[4];
            prefetch4<GUARD>(xp, yp, nx, ny, rbn, rmax, col);
            horiz4<GUARD>(sm + (size_t)(t & 1) * BUFF2, r0 + t * 4, rmax, jrow, g, acc);
            vert4<4, GUARD>(v, sm + (size_t)((t + 1) & 1) * BUFF2,
                            nx, ny, rbn, rmax, sidx);
            __syncthreads();
        }
        if (t + 2 < nsub) {   // horizontal(t+1) + vertical(t+2), rb_next % 8 == 0
            const int rbn = r0 + (t + 2) * 4;
            float nx[4], ny[4];
            prefetch4<GUARD>(xp, yp, nx, ny, rbn, rmax, col);
            horiz4<GUARD>(sm + (size_t)((t + 1) & 1) * BUFF2, r0 + (t + 1) * 4,
                          rmax, jrow, g, acc);
            vert4<0, GUARD>(v, sm + (size_t)((t + 2) & 1) * BUFF2,
                            nx, ny, rbn, rmax, sidx);
            __syncthreads();
        }
    }
    horiz4<GUARD>(sm + (size_t)((nsub - 1) & 1) * BUFF2, r0 + (nsub - 1) * 4,
                  rmax, jrow, g, acc);
    return acc;
}

__global__ __launch_bounds__(512, 2)
void ssim_kernel(const float* __restrict__ X, const float* __restrict__ Y,
                 float* __restrict__ out) {
    extern __shared__ float2 smbuf[];
    __shared__ float wsum[16];
    __shared__ bool isLast;

    const int tid  = threadIdx.x;
    const int band = blockIdx.x;
    const int img  = blockIdx.y;

    const float* __restrict__ xp = X + (size_t)img * (512 * 512);
    const float* __restrict__ yp = Y + (size_t)img * (512 * 512);
    const int r0   = band * BR;
    const int rmax = min(r0 + BR - 1, OH - 1);

    float acc;
    if (rmax == r0 + BR - 1) {
        acc = band_loop<false>(xp, yp, smbuf, r0, rmax, tid);
    } else {
        acc = band_loop<true>(xp, yp, smbuf, r0, rmax, tid);
    }

    // ---- block reduction ----
#pragma unroll
    for (int o = 16; o > 0; o >>= 1)
        acc += __shfl_xor_sync(0xffffffffu, acc, o);
    if ((tid & 31) == 0) wsum[tid >> 5] = acc;
    __syncthreads();

    if (tid == 0) {
        float s = 0.f;
#pragma unroll
        for (int w = 0; w < 16; ++w) s += wsum[w];
        g_partials[img * NBANDS + band] = s;
        __threadfence();
        unsigned int old = atomicAdd(&g_count, 1u);
        isLast = (old == NCTA - 1);
    }
    __syncthreads();

    // ---- deterministic last-block global reduction ----
    if (isLast) {
        float s = 0.f;
        for (int i = tid; i < NCTA; i += 512) s += g_partials[i];
#pragma unroll
        for (int o = 16; o > 0; o >>= 1)
            s += __shfl_xor_sync(0xffffffffu, s, o);
        if ((tid & 31) == 0) wsum[tid >> 5] = s;
        __syncthreads();
        if (tid == 0) {
            float t = 0.f;
#pragma unroll
            for (int w = 0; w < 16; ++w) t += wsum[w];
            out[0] = 1.0f - t * (1.0f / 24579456.0f);  // 96*506*506
            g_count = 0;  // reset for next graph replay
        }
    }
}

extern "C" void kernel_launch(void* const* d_in, const int* in_sizes, int n_in,
                              void* d_out, int out_size) {
    (void)in_sizes; (void)n_in; (void)out_size;
    const float* X = (const float*)d_in[0];
    const float* Y = (const float*)d_in[1];

    cudaFuncSetAttribute(ssim_kernel,
                         cudaFuncAttributeMaxDynamicSharedMemorySize, SMEM_BYTES);

    dim3 grid(NBANDS, NIMG);
    ssim_kernel<<<grid, 512, SMEM_BYTES>>>(X, Y, (float*)d_out);
}